// round 4
// baseline (speedup 1.0000x reference)
#include <cuda_runtime.h>
#include <cstdint>

// Problem constants (fixed by the reference: B=4, T=2048, S=4, D=1024)
#define BT      8192        // B*T
#define SDIM    4
#define DDIM    1024
#define DVEC    256         // D/4 float4 per row
#define SINKHORN_ITERS 20
#define EPS_SK  1e-8f

// ---------------------------------------------------------------------------
// Single fused kernel. Each block = one bt row (256 threads = 256 dvec).
// Thread 0 computes the 4x4 Sinkhorn + scalar folds into shared memory while
// the block's DRAM loads are in flight; __syncthreads; then the 4-stream mix.
//   out[bt,s,dv] = sum_sp M[sp][s]*x[bt,sp,dv] + g[s]*lo[bt,dv]
//                  + bias_res[s,dv] + bias_pos[s,dv]
// ---------------------------------------------------------------------------
__global__ __launch_bounds__(256, 4)
void mhc_residual_fused_kernel(const float4* __restrict__ x,
                               const float4* __restrict__ lo,
                               const float*  __restrict__ H_res,
                               const float*  __restrict__ H_pos,
                               const float*  __restrict__ alpha_res,
                               const float*  __restrict__ alpha_pos,
                               const float4* __restrict__ br,
                               const float4* __restrict__ bp,
                               float4* __restrict__ out)
{
    __shared__ float sM[16];   // M[sp*4+s] = (sp==s) + alpha_res * P[sp][s]
    __shared__ float sg[4];    // alpha_pos * H_pos[s]

    const unsigned dvec = threadIdx.x;          // 0..255
    const unsigned bt   = blockIdx.x;           // 0..8191

    // Front-batch the DRAM-bound loads (in flight during the Sinkhorn below)
    const float4* xr = x + (size_t)bt * (SDIM * DVEC) + dvec;
    float4 x0 = __ldg(xr + 0 * DVEC);
    float4 x1 = __ldg(xr + 1 * DVEC);
    float4 x2 = __ldg(xr + 2 * DVEC);
    float4 x3 = __ldg(xr + 3 * DVEC);
    float4 l  = __ldg(lo + (size_t)bt * DVEC + dvec);

    // Thread 0: 4x4 Sinkhorn projection (redundant per block, hides in the
    // shadow of the loads above; deterministic — identical in every block).
    if (threadIdx.x == 0) {
        float P[4][4];
        #pragma unroll
        for (int r = 0; r < 4; r++) {
            float m = __ldg(H_res + r * 4 + 0);
            #pragma unroll
            for (int c = 1; c < 4; c++) m = fmaxf(m, __ldg(H_res + r * 4 + c));
            #pragma unroll
            for (int c = 0; c < 4; c++) P[r][c] = __expf(__ldg(H_res + r * 4 + c) - m);
        }
        #pragma unroll 1
        for (int it = 0; it < SINKHORN_ITERS; it++) {
            #pragma unroll
            for (int r = 0; r < 4; r++) {
                float s = (P[r][0] + P[r][1]) + (P[r][2] + P[r][3]) + EPS_SK;
                float inv = __frcp_rn(s);
                #pragma unroll
                for (int c = 0; c < 4; c++) P[r][c] *= inv;
            }
            #pragma unroll
            for (int c = 0; c < 4; c++) {
                float s = (P[0][c] + P[1][c]) + (P[2][c] + P[3][c]) + EPS_SK;
                float inv = __frcp_rn(s);
                #pragma unroll
                for (int r = 0; r < 4; r++) P[r][c] *= inv;
            }
        }
        float ar = __ldg(alpha_res);
        float ap = __ldg(alpha_pos);
        #pragma unroll
        for (int sp = 0; sp < 4; sp++)
            #pragma unroll
            for (int s = 0; s < 4; s++)
                sM[sp * 4 + s] = (sp == s ? 1.0f : 0.0f) + ar * P[sp][s];
        #pragma unroll
        for (int s = 0; s < 4; s++)
            sg[s] = ap * __ldg(H_pos + s);
    }
    __syncthreads();

    float4* outr = out + (size_t)bt * (SDIM * DVEC) + dvec;

#pragma unroll
    for (int s = 0; s < 4; s++) {
        float m0 = sM[0 * 4 + s];
        float m1 = sM[1 * 4 + s];
        float m2 = sM[2 * 4 + s];
        float m3 = sM[3 * 4 + s];
        float g  = sg[s];
        // Bias: L2-resident broadcast loads, combined inline (loaded late to
        // keep register liveness below the 64-reg / 4-block boundary)
        float4 a = __ldg(br + s * DVEC + dvec);
        float4 c = __ldg(bp + s * DVEC + dvec);
        float4 b;
        b.x = a.x + c.x; b.y = a.y + c.y; b.z = a.z + c.z; b.w = a.w + c.w;
        float4 o;
        o.x = fmaf(m0, x0.x, fmaf(m1, x1.x, fmaf(m2, x2.x, fmaf(m3, x3.x, fmaf(g, l.x, b.x)))));
        o.y = fmaf(m0, x0.y, fmaf(m1, x1.y, fmaf(m2, x2.y, fmaf(m3, x3.y, fmaf(g, l.y, b.y)))));
        o.z = fmaf(m0, x0.z, fmaf(m1, x1.z, fmaf(m2, x2.z, fmaf(m3, x3.z, fmaf(g, l.z, b.z)))));
        o.w = fmaf(m0, x0.w, fmaf(m1, x1.w, fmaf(m2, x2.w, fmaf(m3, x3.w, fmaf(g, l.w, b.w)))));
        outr[s * DVEC] = o;
    }
}

// ---------------------------------------------------------------------------
// Launch. Inputs per metadata order:
//   0: x (B,T,S,D) f32   1: layer_output (B,T,D) f32   2: H_res (S,S) f32
//   3: H_pos (S,1) f32   4: alpha_res f32 scalar        5: alpha_pos f32 scalar
//   6: bias_res (S,D)    7: bias_pos (S,D)
// ---------------------------------------------------------------------------
extern "C" void kernel_launch(void* const* d_in, const int* in_sizes, int n_in,
                              void* d_out, int out_size)
{
    const float* x         = (const float*)d_in[0];
    const float* lo        = (const float*)d_in[1];
    const float* H_res     = (const float*)d_in[2];
    const float* H_pos     = (const float*)d_in[3];
    const float* alpha_res = (const float*)d_in[4];
    const float* alpha_pos = (const float*)d_in[5];
    const float* bias_res  = (const float*)d_in[6];
    const float* bias_pos  = (const float*)d_in[7];
    float* out             = (float*)d_out;

    mhc_residual_fused_kernel<<<BT, 256>>>(
        (const float4*)x, (const float4*)lo,
        H_res, H_pos, alpha_res, alpha_pos,
        (const float4*)bias_res, (const float4*)bias_pos,
        (float4*)out);
}

// round 5
// speedup vs baseline: 2.1964x; 2.1964x over previous
#include <cuda_runtime.h>
#include <cstdint>

// Problem constants (fixed by the reference: B=4, T=2048, S=4, D=1024)
#define BT      8192        // B*T
#define SDIM    4
#define DDIM    1024
#define DVEC    256         // D/4 float4 per row
#define SINKHORN_ITERS 20
#define EPS_SK  1e-8f

// Device-side scratch (allocation-free rule: use __device__ globals)
__device__ float  d_M[16];                 // M[sp*4+s] = (sp==s) + a_res*P[sp][s]
__device__ float  d_g[4];                  // alpha_pos * H_pos[s]
__device__ float4 d_biasC[SDIM * DVEC];    // bias_res + bias_pos, [s][dvec]

__device__ __forceinline__ float rcp_approx(float x) {
    float r;
    asm("rcp.approx.f32 %0, %1;" : "=f"(r) : "f"(x));
    return r;
}

// ---------------------------------------------------------------------------
// Prep: warp-parallel 4x4 Sinkhorn (lanes 0..15 hold P[r][c], shfl-reduced)
// + 256-thread bias fold. ~2us total.
// ---------------------------------------------------------------------------
__global__ __launch_bounds__(256)
void prep_kernel(const float*  __restrict__ H_res,
                 const float*  __restrict__ H_pos,
                 const float*  __restrict__ alpha_res,
                 const float*  __restrict__ alpha_pos,
                 const float4* __restrict__ br,
                 const float4* __restrict__ bp)
{
    const unsigned tid = threadIdx.x;

    // Bias fold: 1024 float4, 4 per thread (runs on all warps, overlaps warp 0)
    #pragma unroll
    for (int i = 0; i < 4; i++) {
        unsigned j = tid + i * 256;
        float4 a = __ldg(br + j);
        float4 c = __ldg(bp + j);
        float4 b;
        b.x = a.x + c.x; b.y = a.y + c.y; b.z = a.z + c.z; b.w = a.w + c.w;
        d_biasC[j] = b;
    }

    // Warp 0, lanes 0..15: Sinkhorn. lane = r*4 + c.
    if (tid < 16) {
        const unsigned lane = tid;
        const unsigned r = lane >> 2;      // row index (unused directly, layout only)
        (void)r;
        float h = __ldg(H_res + lane);
        // row max over c (lanes differing in bits 0..1)
        float m = fmaxf(h, __shfl_xor_sync(0xffffu, h, 1));
        m = fmaxf(m, __shfl_xor_sync(0xffffu, m, 2));
        float v = __expf(h - m);

        #pragma unroll 1
        for (int it = 0; it < SINKHORN_ITERS; it++) {
            // row sum over c
            float s = v + __shfl_xor_sync(0xffffu, v, 1);
            s += __shfl_xor_sync(0xffffu, s, 2);
            v *= rcp_approx(s + EPS_SK);
            // col sum over r (lanes differing in bits 2..3)
            float t = v + __shfl_xor_sync(0xffffu, v, 4);
            t += __shfl_xor_sync(0xffffu, t, 8);
            v *= rcp_approx(t + EPS_SK);
        }

        float ar = __ldg(alpha_res);
        // d_M[sp*4+s]: lane holds P[r][c] with sp=r, s=c -> direct store
        float diag = ((lane >> 2) == (lane & 3)) ? 1.0f : 0.0f;
        d_M[lane] = diag + ar * v;
        if (lane < 4)
            d_g[lane] = __ldg(alpha_pos) * __ldg(H_pos + lane);
    }
}

// ---------------------------------------------------------------------------
// Main kernel (PDL secondary): issues its DRAM loads first, then waits for
// prep's completion via cudaGridDependencySynchronize before reading d_M.
//   out[bt,s,dv] = sum_sp M[sp][s]*x[bt,sp,dv] + g[s]*lo[bt,dv] + biasC[s,dv]
// ---------------------------------------------------------------------------
__global__ __launch_bounds__(256)
void mhc_residual_kernel(const float4* __restrict__ x,
                         const float4* __restrict__ lo,
                         float4* __restrict__ out)
{
    const unsigned dvec = threadIdx.x;          // 0..255
    const unsigned bt   = blockIdx.x;           // 0..8191

    // Front-batch the DRAM-bound loads — legal before the dependency sync
    // (prep does not write x or lo).
    const float4* xr = x + (size_t)bt * (SDIM * DVEC) + dvec;
    float4 x0 = __ldg(xr + 0 * DVEC);
    float4 x1 = __ldg(xr + 1 * DVEC);
    float4 x2 = __ldg(xr + 2 * DVEC);
    float4 x3 = __ldg(xr + 3 * DVEC);
    float4 l  = __ldg(lo + (size_t)bt * DVEC + dvec);

#if __CUDA_ARCH__ >= 900
    cudaGridDependencySynchronize();   // prep's d_M/d_g/d_biasC now visible
#endif

    __shared__ float sM[16];
    __shared__ float sg[4];
    if (threadIdx.x < 16) sM[threadIdx.x] = d_M[threadIdx.x];
    if (threadIdx.x < 4)  sg[threadIdx.x] = d_g[threadIdx.x];
    __syncthreads();

    float4* outr = out + (size_t)bt * (SDIM * DVEC) + dvec;

#pragma unroll
    for (int s = 0; s < 4; s++) {
        float m0 = sM[0 * 4 + s];
        float m1 = sM[1 * 4 + s];
        float m2 = sM[2 * 4 + s];
        float m3 = sM[3 * 4 + s];
        float g  = sg[s];
        float4 b = d_biasC[s * DVEC + dvec];   // L2-resident broadcast
        float4 o;
        o.x = fmaf(m0, x0.x, fmaf(m1, x1.x, fmaf(m2, x2.x, fmaf(m3, x3.x, fmaf(g, l.x, b.x)))));
        o.y = fmaf(m0, x0.y, fmaf(m1, x1.y, fmaf(m2, x2.y, fmaf(m3, x3.y, fmaf(g, l.y, b.y)))));
        o.z = fmaf(m0, x0.z, fmaf(m1, x1.z, fmaf(m2, x2.z, fmaf(m3, x3.z, fmaf(g, l.z, b.z)))));
        o.w = fmaf(m0, x0.w, fmaf(m1, x1.w, fmaf(m2, x2.w, fmaf(m3, x3.w, fmaf(g, l.w, b.w)))));
        outr[s * DVEC] = o;
    }
}

// ---------------------------------------------------------------------------
// Launch. Inputs per metadata order:
//   0: x (B,T,S,D) f32   1: layer_output (B,T,D) f32   2: H_res (S,S) f32
//   3: H_pos (S,1) f32   4: alpha_res f32 scalar        5: alpha_pos f32 scalar
//   6: bias_res (S,D)    7: bias_pos (S,D)
// ---------------------------------------------------------------------------
extern "C" void kernel_launch(void* const* d_in, const int* in_sizes, int n_in,
                              void* d_out, int out_size)
{
    const float* x         = (const float*)d_in[0];
    const float* lo        = (const float*)d_in[1];
    const float* H_res     = (const float*)d_in[2];
    const float* H_pos     = (const float*)d_in[3];
    const float* alpha_res = (const float*)d_in[4];
    const float* alpha_pos = (const float*)d_in[5];
    const float* bias_res  = (const float*)d_in[6];
    const float* bias_pos  = (const float*)d_in[7];
    float* out             = (float*)d_out;

    prep_kernel<<<1, 256>>>(H_res, H_pos, alpha_res, alpha_pos,
                            (const float4*)bias_res, (const float4*)bias_pos);

    // Secondary launch with programmatic dependent launch: it may begin
    // before prep completes; the kernel itself synchronizes via
    // cudaGridDependencySynchronize before touching prep's outputs.
    cudaLaunchConfig_t cfg = {};
    cfg.gridDim  = dim3(BT, 1, 1);
    cfg.blockDim = dim3(256, 1, 1);
    cfg.dynamicSmemBytes = 0;
    cfg.stream = 0;
    cudaLaunchAttribute attrs[1];
    attrs[0].id = cudaLaunchAttributeProgrammaticStreamSerialization;
    attrs[0].val.programmaticStreamSerializationAllowed = 1;
    cfg.attrs = attrs;
    cfg.numAttrs = 1;

    cudaLaunchKernelEx(&cfg, mhc_residual_kernel,
                       (const float4*)x, (const float4*)lo, (float4*)out);
}